// round 11
// baseline (speedup 1.0000x reference)
#include <cuda_runtime.h>
#include <cuda_fp16.h>
#include <cstdint>

#define B_   256
#define T_   256
#define EMB_ 384
#define H_   64
#define M_   (B_*T_)

// Scratch: q,k,v projections in fp16 (q pre-scaled by 384^-.5*log2e).
__device__ __align__(16) __half g_qkv[3][(size_t)M_ * H_];

#define SW128(o) ((o) ^ ((((uint32_t)(o)) >> 3) & 0x70))

// 384^-0.5 * log2(e)
#define QSCALE (0.05103103630798287f * 1.4426950408889634f)

__device__ __forceinline__ uint32_t smem_u32(const void* p) {
    uint32_t a;
    asm("{ .reg .u64 t; cvta.to.shared.u64 t, %1; cvt.u32.u64 %0, t; }"
        : "=r"(a) : "l"(p));
    return a;
}

__device__ __forceinline__ void ldsm4(uint32_t* r, uint32_t addr) {
    asm volatile("ldmatrix.sync.aligned.m8n8.x4.shared.b16 {%0,%1,%2,%3}, [%4];"
                 : "=r"(r[0]), "=r"(r[1]), "=r"(r[2]), "=r"(r[3]) : "r"(addr));
}

__device__ __forceinline__ void ldsm4t(uint32_t* r, uint32_t addr) {
    asm volatile("ldmatrix.sync.aligned.m8n8.x4.trans.shared.b16 {%0,%1,%2,%3}, [%4];"
                 : "=r"(r[0]), "=r"(r[1]), "=r"(r[2]), "=r"(r[3]) : "r"(addr));
}

__device__ __forceinline__ void mma16816h(float* d, const uint32_t* a,
                                          uint32_t b0, uint32_t b1) {
    asm volatile(
        "mma.sync.aligned.m16n8k16.row.col.f32.f16.f16.f32 "
        "{%0,%1,%2,%3}, {%4,%5,%6,%7}, {%8,%9}, {%0,%1,%2,%3};"
        : "+f"(d[0]), "+f"(d[1]), "+f"(d[2]), "+f"(d[3])
        : "r"(a[0]), "r"(a[1]), "r"(a[2]), "r"(a[3]), "r"(b0), "r"(b1));
}

__device__ __forceinline__ uint32_t pack_h2(float a, float b) {
    uint32_t r;
    asm("cvt.rn.f16x2.f32 %0, %1, %2;" : "=r"(r) : "f"(b), "f"(a));
    return r;
}

__device__ __forceinline__ void cp_async16(uint32_t saddr, const void* g) {
    asm volatile("cp.async.cg.shared.global [%0], [%1], 16;" :: "r"(saddr), "l"(g));
}
#define CP_COMMIT() asm volatile("cp.async.commit_group;" ::: "memory")
#define CP_WAIT0()  asm volatile("cp.async.wait_group 0;" ::: "memory")

// ---------------------------------------------------------------------------
// Kernel 1: QKV projection, fp16 mma, pipelined. 512 threads / 16 warps.
// W converted fp32->fp16 in-flight, stored in natural [k][n] layout,
// B-fragments via ldsm4t (no wconv kernel, no pre-transposed copy).
// Warp tile: 32 rows x 48 cols (4x4 warp grid over 128 x 192).
// smem: x stages 2 x 16K at 0; W stages 2 x 24K at 32768. 80 KB.
// ---------------------------------------------------------------------------
#define SM_W0    32768
#define SMEM_SZ  (SM_W0 + 2*24576)

__device__ __forceinline__ void ldg_x(float4* xr, const float* __restrict__ xb,
                                      int k0, int tid) {
    #pragma unroll
    for (int it = 0; it < 4; it++) {
        int f = tid + it * 512;
        xr[it] = *(const float4*)&xb[(size_t)(f >> 4) * EMB_ + k0 + (f & 15) * 4];
    }
}

__device__ __forceinline__ void sts_x(const float4* xr, char* xs, int tid) {
    #pragma unroll
    for (int it = 0; it < 4; it++) {
        int f = tid + it * 512;
        uint32_t off = SW128((f >> 4) * 128 + (f & 15) * 8);
        uint2 p;
        p.x = pack_h2(xr[it].x, xr[it].y);
        p.y = pack_h2(xr[it].z, xr[it].w);
        *(uint2*)(xs + off) = p;
    }
}

// W chunk: 3 matrices x 64 k-rows x 64 n. Each thread: 6 float4 (4 n each).
__device__ __forceinline__ void ldg_w(float4* wr, const float* __restrict__ Wq,
                                      const float* __restrict__ Wk,
                                      const float* __restrict__ Wv,
                                      int k0, int tid) {
    #pragma unroll
    for (int it = 0; it < 6; it++) {
        int f  = tid + it * 512;        // 0..3071
        int w2 = f >> 10;
        int r  = f & 1023;
        int k  = r >> 4;
        int n4 = (r & 15) * 4;
        const float* W = (w2 == 0) ? Wq : (w2 == 1) ? Wk : Wv;
        wr[it] = *(const float4*)&W[(size_t)(k0 + k) * H_ + n4];
    }
}

__device__ __forceinline__ void sts_w(const float4* wr, char* ws, int tid) {
    #pragma unroll
    for (int it = 0; it < 6; it++) {
        int f  = tid + it * 512;
        int w2 = f >> 10;
        int r  = f & 1023;
        int k  = r >> 4;
        int n4 = (r & 15) * 4;
        const float s = (w2 == 0) ? QSCALE : 1.0f;
        uint2 p;
        p.x = pack_h2(wr[it].x * s, wr[it].y * s);
        p.y = pack_h2(wr[it].z * s, wr[it].w * s);
        *(uint2*)(ws + w2 * 8192 + SW128(k * 128 + n4 * 2)) = p;
    }
}

__global__ __launch_bounds__(512) void qkv_mm(const float* __restrict__ x,
                                              const float* __restrict__ Wq,
                                              const float* __restrict__ Wk,
                                              const float* __restrict__ Wv)
{
    extern __shared__ char smem[];
    const uint32_t sb = smem_u32(smem);
    const int tid  = threadIdx.x;
    const int wid  = tid >> 5;
    const int lane = tid & 31;
    const int m0   = blockIdx.x * 128;
    const float* xb = x + (size_t)m0 * EMB_;

    const int wr_ = wid & 3;           // row group: rows wr_*32 .. +32
    const int wc  = wid >> 2;          // col group: cols wc*48 .. +48
    const int r_base = wr_ * 32;
    const int c_base = wc * 48;

    float acc[2][6][4] = {};

    const int lrow   = (lane & 7) + ((lane >> 3) & 1) * 8;
    const int a_colb = ((lane >> 4) & 1) * 16;
    const int lcolh  = ((lane >> 4) & 1) * 16;   // for ldsm4t B

    float4 xr[4];
    float4 wreg[6];
    ldg_x(xr, xb, 0, tid);
    ldg_w(wreg, Wq, Wk, Wv, 0, tid);

    #pragma unroll 1
    for (int c = 0; c < 6; c++) {
        const int st = c & 1;
        sts_x(xr, smem + st * 16384, tid);
        sts_w(wreg, smem + SM_W0 + st * 24576, tid);
        __syncthreads();

        if (c < 5) {
            ldg_x(xr, xb, (c + 1) * 64, tid);
            ldg_w(wreg, Wq, Wk, Wv, (c + 1) * 64, tid);
        }

        const uint32_t xs = sb + st * 16384;
        const uint32_t wbase = sb + SM_W0 + st * 24576;
        #pragma unroll
        for (int ks = 0; ks < 4; ks++) {
            uint32_t a0[4], a1[4];
            ldsm4(a0, xs + SW128((r_base + lrow)      * 128 + ks * 32 + a_colb));
            ldsm4(a1, xs + SW128((r_base + 16 + lrow) * 128 + ks * 32 + a_colb));
            #pragma unroll
            for (int np = 0; np < 3; np++) {
                const int colb = c_base + np * 16;
                const int w2   = colb >> 6;
                const int nloc = colb & 63;
                uint32_t bb[4];
                // W is [k][n] in smem; trans-ldmatrix yields col-major B frags:
                // bb[0]=n0-7/k0-7, bb[1]=n0-7/k8-15, bb[2]=n8-15/k0-7, bb[3]=n8-15/k8-15
                ldsm4t(bb, wbase + w2 * 8192 +
                           SW128((ks * 16 + lrow) * 128 + nloc * 2 + lcolh));
                mma16816h(acc[0][2*np],   a0, bb[0], bb[1]);
                mma16816h(acc[0][2*np+1], a0, bb[2], bb[3]);
                mma16816h(acc[1][2*np],   a1, bb[0], bb[1]);
                mma16816h(acc[1][2*np+1], a1, bb[2], bb[3]);
            }
        }
    }

    // epilogue: pack fp16, store uint32 per 2 cols
    const int g  = lane >> 2;
    const int c2 = (lane & 3) * 2;
    #pragma unroll
    for (int rg = 0; rg < 2; rg++) {
        const int r0 = m0 + r_base + rg * 16 + g;
        #pragma unroll
        for (int nt = 0; nt < 6; nt++) {
            int col = c_base + nt * 8 + c2;
            int w2  = col >> 6;
            int n   = col & 63;
            *(uint32_t*)&g_qkv[w2][(size_t)r0 * H_ + n] =
                pack_h2(acc[rg][nt][0], acc[rg][nt][1]);
            *(uint32_t*)&g_qkv[w2][(size_t)(r0 + 8) * H_ + n] =
                pack_h2(acc[rg][nt][2], acc[rg][nt][3]);
        }
    }
}

// ---------------------------------------------------------------------------
// Kernel 2: fp16 tensor-core causal attention (unchanged from R10).
// smem: Q 32K at 0, K 32K at 32768, V 32K at 65536.  96 KB -> 2 CTAs/SM.
// ---------------------------------------------------------------------------
#define ATTN_SMEM 98304

__global__ __launch_bounds__(256) void attn_tc(float* __restrict__ out)
{
    extern __shared__ char smem[];
    const uint32_t sb = smem_u32(smem);
    const int b    = blockIdx.x;
    const int tid  = threadIdx.x;
    const int wid  = tid >> 5;
    const int lane = tid & 31;

    const __half* qh = g_qkv[0] + (size_t)b * T_ * H_;
    const __half* kh = g_qkv[1] + (size_t)b * T_ * H_;
    const __half* vh = g_qkv[2] + (size_t)b * T_ * H_;

    #pragma unroll
    for (int it = 0; it < 8; it++) {
        int f  = tid + it * 256;
        int j  = f >> 3;
        int q8 = f & 7;
        uint32_t off = SW128(j * 128 + q8 * 16);
        size_t  gof = (size_t)j * H_ + q8 * 8;
        cp_async16(sb + off,         &qh[gof]);
        cp_async16(sb + 32768 + off, &kh[gof]);
        cp_async16(sb + 65536 + off, &vh[gof]);
    }
    CP_COMMIT();
    CP_WAIT0();
    __syncthreads();

    const int g  = lane >> 2;
    const int c4 = lane & 3;
    const int lrow  = (lane & 7) + ((lane >> 3) & 1) * 8;
    const int lcolh = ((lane >> 4) & 1) * 16;

    const uint32_t qbase = sb;
    const uint32_t kbase = sb + 32768;
    const uint32_t vbase = sb + 65536;

    #pragma unroll 1
    for (int half = 0; half < 2; half++) {
        const int tt = (half == 0) ? wid : 15 - wid;
        const int r0 = tt * 16;

        uint32_t qf[4][4];
        #pragma unroll
        for (int kc = 0; kc < 4; kc++)
            ldsm4(qf[kc], qbase + SW128((r0 + lrow) * 128 + kc * 32 + lcolh));

        float oacc[8][4] = {};
        float sum0 = 0.0f, sum1 = 0.0f;
        const int nb = (r0 + 47) >> 5;

        #pragma unroll 1
        for (int blk = 0; blk < nb; blk++) {
            const int s0 = blk * 32;
            float sacc[4][4] = {};

            #pragma unroll
            for (int kc = 0; kc < 4; kc++) {
                uint32_t bh[8];
                #pragma unroll
                for (int grp = 0; grp < 2; grp++) {
                    uint32_t off = SW128((s0 + grp * 16 + lrow) * 128 + kc * 32 + lcolh);
                    ldsm4(&bh[grp * 4], kbase + off);
                }
                #pragma unroll
                for (int nt = 0; nt < 4; nt++) {
                    const int base = (nt >> 1) * 4;
                    mma16816h(sacc[nt], qf[kc],
                              bh[base + (nt & 1)], bh[base + (nt & 1) + 2]);
                }
            }

            const bool last = (blk == nb - 1);
            float p[4][4];
            #pragma unroll
            for (int nt = 0; nt < 4; nt++) {
                #pragma unroll
                for (int rr = 0; rr < 4; rr++) {
                    int j = s0 + nt * 8 + 2 * c4 + (rr & 1);
                    int t = r0 + g + (rr >> 1) * 8;
                    float e = (!last || j <= t) ? exp2f(sacc[nt][rr]) : 0.0f;
                    p[nt][rr] = e;
                    if (rr < 2) sum0 += e; else sum1 += e;
                }
            }

            uint32_t pf[2][4];
            #pragma unroll
            for (int kc2 = 0; kc2 < 2; kc2++) {
                const float* p0 = p[2 * kc2];
                const float* p1 = p[2 * kc2 + 1];
                pf[kc2][0] = pack_h2(p0[0], p0[1]);
                pf[kc2][1] = pack_h2(p0[2], p0[3]);
                pf[kc2][2] = pack_h2(p1[0], p1[1]);
                pf[kc2][3] = pack_h2(p1[2], p1[3]);
            }

            #pragma unroll
            for (int kc2 = 0; kc2 < 2; kc2++) {
                #pragma unroll
                for (int np = 0; np < 4; np++) {
                    uint32_t off = SW128((s0 + kc2 * 16 + lrow) * 128 + np * 32 + lcolh);
                    uint32_t vb[4];
                    ldsm4t(vb, vbase + off);
                    mma16816h(oacc[2*np],   pf[kc2], vb[0], vb[1]);
                    mma16816h(oacc[2*np+1], pf[kc2], vb[2], vb[3]);
                }
            }
        }

        sum0 += __shfl_xor_sync(0xffffffffu, sum0, 1);
        sum0 += __shfl_xor_sync(0xffffffffu, sum0, 2);
        sum1 += __shfl_xor_sync(0xffffffffu, sum1, 1);
        sum1 += __shfl_xor_sync(0xffffffffu, sum1, 2);
        const float inv0 = 1.0f / sum0;
        const float inv1 = 1.0f / sum1;

        float* orow0 = out + ((size_t)b * T_ + r0 + g) * H_;
        float* orow1 = out + ((size_t)b * T_ + r0 + g + 8) * H_;
        #pragma unroll
        for (int nt = 0; nt < 8; nt++) {
            int n = nt * 8 + 2 * c4;
            *(float2*)&orow0[n] = make_float2(oacc[nt][0] * inv0, oacc[nt][1] * inv0);
            *(float2*)&orow1[n] = make_float2(oacc[nt][2] * inv1, oacc[nt][3] * inv1);
        }
    }
}

// ---------------------------------------------------------------------------
extern "C" void kernel_launch(void* const* d_in, const int* in_sizes, int n_in,
                              void* d_out, int out_size)
{
    const float* x  = (const float*)d_in[0];
    const float* Wq = (const float*)d_in[1];
    const float* Wk = (const float*)d_in[2];
    const float* Wv = (const float*)d_in[3];
    float* out = (float*)d_out;
    (void)in_sizes; (void)n_in; (void)out_size;

    cudaFuncSetAttribute(qkv_mm, cudaFuncAttributeMaxDynamicSharedMemorySize, SMEM_SZ);
    qkv_mm<<<M_ / 128, 512, SMEM_SZ>>>(x, Wq, Wk, Wv);

    cudaFuncSetAttribute(attn_tc, cudaFuncAttributeMaxDynamicSharedMemorySize, ATTN_SMEM);
    attn_tc<<<B_, 256, ATTN_SMEM>>>(out);
}

// round 12
// speedup vs baseline: 1.4628x; 1.4628x over previous
#include <cuda_runtime.h>
#include <cuda_fp16.h>
#include <cstdint>

#define B_   256
#define T_   256
#define EMB_ 384
#define H_   64

// fp16 weights [w][n][k]; Wq pre-scaled by 384^-.5*log2e.
__device__ __align__(16) __half g_wt[3][H_][EMB_];

#define SW128(o) ((o) ^ ((((uint32_t)(o)) >> 3) & 0x70))
#define QSCALE (0.05103103630798287f * 1.4426950408889634f)

__device__ __forceinline__ uint32_t smem_u32(const void* p) {
    uint32_t a;
    asm("{ .reg .u64 t; cvta.to.shared.u64 t, %1; cvt.u32.u64 %0, t; }"
        : "=r"(a) : "l"(p));
    return a;
}

__device__ __forceinline__ void ldsm4(uint32_t* r, uint32_t addr) {
    asm volatile("ldmatrix.sync.aligned.m8n8.x4.shared.b16 {%0,%1,%2,%3}, [%4];"
                 : "=r"(r[0]), "=r"(r[1]), "=r"(r[2]), "=r"(r[3]) : "r"(addr));
}

__device__ __forceinline__ void ldsm4t(uint32_t* r, uint32_t addr) {
    asm volatile("ldmatrix.sync.aligned.m8n8.x4.trans.shared.b16 {%0,%1,%2,%3}, [%4];"
                 : "=r"(r[0]), "=r"(r[1]), "=r"(r[2]), "=r"(r[3]) : "r"(addr));
}

__device__ __forceinline__ void mma16816h(float* d, const uint32_t* a,
                                          uint32_t b0, uint32_t b1) {
    asm volatile(
        "mma.sync.aligned.m16n8k16.row.col.f32.f16.f16.f32 "
        "{%0,%1,%2,%3}, {%4,%5,%6,%7}, {%8,%9}, {%0,%1,%2,%3};"
        : "+f"(d[0]), "+f"(d[1]), "+f"(d[2]), "+f"(d[3])
        : "r"(a[0]), "r"(a[1]), "r"(a[2]), "r"(a[3]), "r"(b0), "r"(b1));
}

__device__ __forceinline__ uint32_t pack_h2(float a, float b) {
    uint32_t r;
    asm("cvt.rn.f16x2.f32 %0, %1, %2;" : "=r"(r) : "f"(b), "f"(a));
    return r;
}

__device__ __forceinline__ void cp_async16(uint32_t saddr, const void* g) {
    asm volatile("cp.async.cg.shared.global [%0], [%1], 16;" :: "r"(saddr), "l"(g));
}
#define CP_COMMIT() asm volatile("cp.async.commit_group;" ::: "memory")
#define CP_WAIT0()  asm volatile("cp.async.wait_group 0;" ::: "memory")

// ---------------------------------------------------------------------------
// Kernel 0: W -> fp16, transposed to [n][k]; Wq pre-scaled. (R10, validated)
// ---------------------------------------------------------------------------
__global__ void wconv(const float* __restrict__ Wq, const float* __restrict__ Wk,
                      const float* __restrict__ Wv) {
    int idx = blockIdx.x * 256 + threadIdx.x;
    if (idx >= 3 * H_ * (EMB_ / 4)) return;
    int w  = idx / (H_ * (EMB_ / 4));
    int r  = idx % (H_ * (EMB_ / 4));
    int n  = r / (EMB_ / 4);
    int k4 = (r % (EMB_ / 4)) * 4;
    const float* W = (w == 0) ? Wq : (w == 1) ? Wk : Wv;
    const float s = (w == 0) ? QSCALE : 1.0f;
    uint2 p;
    p.x = pack_h2(W[(k4 + 0) * H_ + n] * s, W[(k4 + 1) * H_ + n] * s);
    p.y = pack_h2(W[(k4 + 2) * H_ + n] * s, W[(k4 + 3) * H_ + n] * s);
    *(uint2*)&g_wt[w][n][k4] = p;
}

// ---------------------------------------------------------------------------
// Fused kernel: per-batch QKV projection (fp16 mma) + causal attention.
// 512 threads / 16 warps, 1 CTA per batch.
// smem layout:
//   Q 0..32K, K 32K..64K, V 64K..96K     (fp16, SW128 row*128+n*2)
//   x stages 2 x 16K at 98304
//   W stages 2 x 24K at 131072           (total 176 KB)
// GEMM: two M-passes of 128 rows; warp tile 32 rows x 48 cols (R10 loop).
// Attention: warp = m-tile wid (16 rows), flash-style no-max softmax (R10).
// ---------------------------------------------------------------------------
#define SM_X     98304
#define SM_WS    131072
#define SMEM_SZ  (SM_WS + 2*24576)

__device__ __forceinline__ void ldg_x(float4* xr, const float* __restrict__ xb,
                                      int k0, int tid) {
    #pragma unroll
    for (int it = 0; it < 4; it++) {
        int f = tid + it * 512;
        xr[it] = *(const float4*)&xb[(size_t)(f >> 4) * EMB_ + k0 + (f & 15) * 4];
    }
}

__device__ __forceinline__ void sts_x(const float4* xr, char* xs, int tid) {
    #pragma unroll
    for (int it = 0; it < 4; it++) {
        int f = tid + it * 512;
        uint32_t off = SW128((f >> 4) * 128 + (f & 15) * 8);
        uint2 p;
        p.x = pack_h2(xr[it].x, xr[it].y);
        p.y = pack_h2(xr[it].z, xr[it].w);
        *(uint2*)(xs + off) = p;
    }
}

__device__ __forceinline__ void cp_w(uint32_t wdst, int k0, int tid) {
    #pragma unroll
    for (int it = 0; it < 3; it++) {
        int f  = tid + it * 512;
        int w2 = f >> 9;
        int r  = f & 511;
        int n  = r >> 3;
        int q8 = r & 7;
        cp_async16(wdst + w2 * 8192 + SW128(n * 128 + q8 * 16),
                   &g_wt[w2][n][k0 + q8 * 8]);
    }
}

__global__ __launch_bounds__(512) void qkv_attn(const float* __restrict__ x,
                                                float* __restrict__ out)
{
    extern __shared__ char smem[];
    const uint32_t sb = smem_u32(smem);
    const int b    = blockIdx.x;
    const int tid  = threadIdx.x;
    const int wid  = tid >> 5;
    const int lane = tid & 31;

    const int lrow   = (lane & 7) + ((lane >> 3) & 1) * 8;
    const int a_colb = ((lane >> 4) & 1) * 16;
    const int b_n    = (lane >> 4) * 8 + (lane & 7);
    const int b_colb = ((lane >> 3) & 1) * 16;
    const int g      = lane >> 2;
    const int c4     = lane & 3;

    // ======================= Phase 1: QKV projection =======================
    const int wr_ = wid & 3;
    const int wc  = wid >> 2;
    const int r_base = wr_ * 32;
    const int c_base = wc * 48;

    #pragma unroll 1
    for (int pass = 0; pass < 2; pass++) {
        const float* xb = x + ((size_t)b * T_ + pass * 128) * EMB_;
        float acc[2][6][4] = {};

        float4 xr[4];
        ldg_x(xr, xb, 0, tid);
        cp_w(sb + SM_WS, 0, tid);
        CP_COMMIT();

        #pragma unroll 1
        for (int c = 0; c < 6; c++) {
            const int st = c & 1;
            sts_x(xr, smem + SM_X + st * 16384, tid);
            CP_WAIT0();
            __syncthreads();

            if (c < 5) {
                ldg_x(xr, xb, (c + 1) * 64, tid);
                cp_w(sb + SM_WS + (st ^ 1) * 24576, (c + 1) * 64, tid);
                CP_COMMIT();
            }

            const uint32_t xs = sb + SM_X + st * 16384;
            const uint32_t wbase = sb + SM_WS + st * 24576;
            #pragma unroll
            for (int ks = 0; ks < 4; ks++) {
                uint32_t a0[4], a1[4];
                ldsm4(a0, xs + SW128((r_base + lrow)      * 128 + ks * 32 + a_colb));
                ldsm4(a1, xs + SW128((r_base + 16 + lrow) * 128 + ks * 32 + a_colb));
                #pragma unroll
                for (int np = 0; np < 3; np++) {
                    const int colb = c_base + np * 16;
                    const uint32_t wt = wbase + (colb >> 6) * 8192;
                    const int nloc = colb & 63;
                    uint32_t bb[4];
                    ldsm4(bb, wt + SW128((nloc + b_n) * 128 + ks * 32 + b_colb));
                    mma16816h(acc[0][2*np],   a0, bb[0], bb[1]);
                    mma16816h(acc[0][2*np+1], a0, bb[2], bb[3]);
                    mma16816h(acc[1][2*np],   a1, bb[0], bb[1]);
                    mma16816h(acc[1][2*np+1], a1, bb[2], bb[3]);
                }
            }
        }

        // epilogue: pack fp16 straight into smem Q/K/V tiles
        const int c2 = c4 * 2;
        #pragma unroll
        for (int rg = 0; rg < 2; rg++) {
            const int row = pass * 128 + r_base + rg * 16 + g;
            #pragma unroll
            for (int nt = 0; nt < 6; nt++) {
                int col = c_base + nt * 8 + c2;
                int w2  = col >> 6;
                int n   = col & 63;
                char* dst = smem + w2 * 32768;
                *(uint32_t*)(dst + SW128(row * 128 + n * 2)) =
                    pack_h2(acc[rg][nt][0], acc[rg][nt][1]);
                *(uint32_t*)(dst + SW128((row + 8) * 128 + n * 2)) =
                    pack_h2(acc[rg][nt][2], acc[rg][nt][3]);
            }
        }
    }
    __syncthreads();

    // ======================= Phase 2: causal attention ======================
    const uint32_t qbase = sb;
    const uint32_t kbase = sb + 32768;
    const uint32_t vbase = sb + 65536;
    const int lcolh = a_colb;

    const int r0 = wid * 16;

    uint32_t qf[4][4];
    #pragma unroll
    for (int kc = 0; kc < 4; kc++)
        ldsm4(qf[kc], qbase + SW128((r0 + lrow) * 128 + kc * 32 + lcolh));

    float oacc[8][4] = {};
    float sum0 = 0.0f, sum1 = 0.0f;
    const int nb = (r0 + 47) >> 5;

    #pragma unroll 1
    for (int blk = 0; blk < nb; blk++) {
        const int s0 = blk * 32;
        float sacc[4][4] = {};

        // ---- S = Q K^T ----
        #pragma unroll
        for (int kc = 0; kc < 4; kc++) {
            uint32_t bh[8];
            #pragma unroll
            for (int grp = 0; grp < 2; grp++) {
                uint32_t off = SW128((s0 + grp * 16 + lrow) * 128 + kc * 32 + lcolh);
                ldsm4(&bh[grp * 4], kbase + off);
            }
            #pragma unroll
            for (int nt = 0; nt < 4; nt++) {
                const int base = (nt >> 1) * 4;
                mma16816h(sacc[nt], qf[kc],
                          bh[base + (nt & 1)], bh[base + (nt & 1) + 2]);
            }
        }

        // ---- exp2 + causal mask + rowsum ----
        const bool last = (blk == nb - 1);
        float p[4][4];
        #pragma unroll
        for (int nt = 0; nt < 4; nt++) {
            #pragma unroll
            for (int rr = 0; rr < 4; rr++) {
                int j = s0 + nt * 8 + 2 * c4 + (rr & 1);
                int t = r0 + g + (rr >> 1) * 8;
                float e = (!last || j <= t) ? exp2f(sacc[nt][rr]) : 0.0f;
                p[nt][rr] = e;
                if (rr < 2) sum0 += e; else sum1 += e;
            }
        }

        // ---- P fragments, fp16 ----
        uint32_t pf[2][4];
        #pragma unroll
        for (int kc2 = 0; kc2 < 2; kc2++) {
            const float* p0 = p[2 * kc2];
            const float* p1 = p[2 * kc2 + 1];
            pf[kc2][0] = pack_h2(p0[0], p0[1]);
            pf[kc2][1] = pack_h2(p0[2], p0[3]);
            pf[kc2][2] = pack_h2(p1[0], p1[1]);
            pf[kc2][3] = pack_h2(p1[2], p1[3]);
        }

        // ---- O += P V ----
        #pragma unroll
        for (int kc2 = 0; kc2 < 2; kc2++) {
            #pragma unroll
            for (int np = 0; np < 4; np++) {
                uint32_t off = SW128((s0 + kc2 * 16 + lrow) * 128 + np * 32 + lcolh);
                uint32_t vb[4];
                ldsm4t(vb, vbase + off);
                mma16816h(oacc[2*np],   pf[kc2], vb[0], vb[1]);
                mma16816h(oacc[2*np+1], pf[kc2], vb[2], vb[3]);
            }
        }
    }

    // ---- rowsum reduce, scale, store ----
    sum0 += __shfl_xor_sync(0xffffffffu, sum0, 1);
    sum0 += __shfl_xor_sync(0xffffffffu, sum0, 2);
    sum1 += __shfl_xor_sync(0xffffffffu, sum1, 1);
    sum1 += __shfl_xor_sync(0xffffffffu, sum1, 2);
    const float inv0 = 1.0f / sum0;
    const float inv1 = 1.0f / sum1;

    float* orow0 = out + ((size_t)b * T_ + r0 + g) * H_;
    float* orow1 = out + ((size_t)b * T_ + r0 + g + 8) * H_;
    #pragma unroll
    for (int nt = 0; nt < 8; nt++) {
        int n = nt * 8 + 2 * c4;
        *(float2*)&orow0[n] = make_float2(oacc[nt][0] * inv0, oacc[nt][1] * inv0);
        *(float2*)&orow1[n] = make_float2(oacc[nt][2] * inv1, oacc[nt][3] * inv1);
    }
}

// ---------------------------------------------------------------------------
extern "C" void kernel_launch(void* const* d_in, const int* in_sizes, int n_in,
                              void* d_out, int out_size)
{
    const float* x  = (const float*)d_in[0];
    const float* Wq = (const float*)d_in[1];
    const float* Wk = (const float*)d_in[2];
    const float* Wv = (const float*)d_in[3];
    float* out = (float*)d_out;
    (void)in_sizes; (void)n_in; (void)out_size;

    wconv<<<(3 * H_ * (EMB_ / 4) + 255) / 256, 256>>>(Wq, Wk, Wv);

    cudaFuncSetAttribute(qkv_attn, cudaFuncAttributeMaxDynamicSharedMemorySize, SMEM_SZ);
    qkv_attn<<<B_, 512, SMEM_SZ>>>(x, out);
}